// round 14
// baseline (speedup 1.0000x reference)
#include <cuda_runtime.h>
#include <cuda_fp16.h>
#include <cstdint>

#define HH    256
#define WW    256
#define BATCH 16
#define CIN   64
#define COUT  64
#define NTHR  576          // 16 compute warps + 2 producer warps

// ---- smem layout (byte offsets from 1024-aligned base) ---------------------
#define RING       4
#define XROW_SPLIT (130 * 128)            // 16640 B: one split (hi or lo) of a row
#define ROWBUF     (2 * XROW_SPLIT)       // 33280
#define XS_BYTES   (RING * ROWBUF)        // 133120
#define WB_OFF     XS_BYTES
#define WTAP       8192                   // 64 co x 64 ci fp16, swizzled
#define WB_BYTES   (9 * WTAP)             // 73728
#define SMEM_REQ   (WB_OFF + WB_BYTES + 1024 + 64)  // align slack -> 207936

// Scratch globals
__device__ __align__(16) __half d_Wh[9 * 64 * 64];  // [tap][co][ci] pre-swizzled
__device__ float d_g[COUT];      // (gamma*istd*wscale)/s   -- quant-folded
__device__ float d_bias[COUT];   // (beta - mean*gamma*istd)/s
__device__ float d_s;            // act quant step s

__device__ __forceinline__ uint32_t smem_u32(const void* p) {
    uint32_t a;
    asm("{ .reg .u64 t; cvta.to.shared.u64 t, %1; cvt.u32.u64 %0, t; }" : "=r"(a) : "l"(p));
    return a;
}
__device__ __forceinline__ void ldsm_x4(uint32_t* r, uint32_t addr) {
    asm volatile("ldmatrix.sync.aligned.m8n8.x4.shared.b16 {%0,%1,%2,%3}, [%4];"
                 : "=r"(r[0]), "=r"(r[1]), "=r"(r[2]), "=r"(r[3]) : "r"(addr));
}
__device__ __forceinline__ void mma16816(float* c, const uint32_t* a,
                                         uint32_t b0, uint32_t b1) {
    asm volatile("mma.sync.aligned.m16n8k16.row.col.f32.f16.f16.f32 "
                 "{%0,%1,%2,%3}, {%4,%5,%6,%7}, {%8,%9}, {%0,%1,%2,%3};"
                 : "+f"(c[0]), "+f"(c[1]), "+f"(c[2]), "+f"(c[3])
                 : "r"(a[0]), "r"(a[1]), "r"(a[2]), "r"(a[3]), "r"(b0), "r"(b1));
}

// swizzled byte offset for (slot row, 16B group): conflict-free ldsm w/o padding
__device__ __forceinline__ uint32_t swz(uint32_t slot, uint32_t g) {
    return slot * 128u + ((g ^ (slot & 7u)) << 4);
}

#define BAR_ARRIVE_1() asm volatile("bar.arrive 1, %0;" :: "n"(NTHR) : "memory")
#define BAR_SYNC_1()   asm volatile("bar.sync 1, %0;"   :: "n"(NTHR) : "memory")

// ---------------- prep: int4 fake-quant weights + BN/act-quant fold ---------
__global__ void prep_kernel(const float* __restrict__ W,
                            const float* __restrict__ gamma,
                            const float* __restrict__ beta,
                            const float* __restrict__ mean,
                            const float* __restrict__ var,
                            const float* __restrict__ act_scale) {
    int co = blockIdx.x;
    __shared__ float red[256];
    float m = 0.f;
    for (int i = threadIdx.x; i < CIN * 9; i += 256)
        m = fmaxf(m, fabsf(W[co * CIN * 9 + i]));
    red[threadIdx.x] = m;
    __syncthreads();
    for (int s = 128; s > 0; s >>= 1) {
        if (threadIdx.x < s)
            red[threadIdx.x] = fmaxf(red[threadIdx.x], red[threadIdx.x + s]);
        __syncthreads();
    }
    float scale = fmaxf(red[0] / 7.0f, 1e-8f);

    for (int i = threadIdx.x; i < CIN * 9; i += 256) {
        int ci = i / 9, r = i - ci * 9;
        float n = rintf(W[co * CIN * 9 + i] / scale);   // round-half-even
        n = fminf(fmaxf(n, -7.f), 7.f);                 // small int -> fp16 exact
        d_Wh[r * 4096 + co * 64 + (((ci >> 3) ^ (co & 7)) << 3) + (ci & 7)] =
            __float2half_rn(n);
    }
    if (threadIdx.x == 0) {
        float s = fmaxf(act_scale[0], 1e-8f);
        float istd = 1.0f / sqrtf(var[co] + 1e-5f);
        // fold weight scale AND 1/s into the BN affine (kills per-output div)
        d_g[co]    = gamma[co] * istd * scale / s;
        d_bias[co] = (beta[co] - mean[co] * gamma[co] * istd) / s;
        if (co == 0) d_s = s;
    }
}

// ---------------- generic staging (prologue; all threads) -------------------
__device__ __forceinline__ void stage_row(const float* __restrict__ xb,
                                          char* basep, int R, int w0,
                                          int tid, int nthr) {
    char* dst = basep + ((R + RING) & (RING - 1)) * ROWBUF;
    bool rvalid = (unsigned)R < (unsigned)HH;
    for (int idx = tid; idx < 130 * 8; idx += nthr) {
        int oct = idx / 130;
        int w   = idx - oct * 130;
        int gw  = w0 - 1 + w;
        uint32_t hi[4] = {0, 0, 0, 0}, lo[4] = {0, 0, 0, 0};
        if (rvalid && (unsigned)gw < (unsigned)WW) {
            const float* p = xb + (size_t)(oct * 8) * (HH * WW) + R * WW + gw;
            #pragma unroll
            for (int j = 0; j < 4; j++) {
                float f0 = p[(2 * j)     * (HH * WW)];
                float f1 = p[(2 * j + 1) * (HH * WW)];
                __half h0 = __float2half_rn(f0);
                __half h1 = __float2half_rn(f1);
                __half l0 = __float2half_rn(f0 - __half2float(h0));
                __half l1 = __float2half_rn(f1 - __half2float(h1));
                __half2 hp = __halves2half2(h0, h1);
                __half2 lp = __halves2half2(l0, l1);
                hi[j] = *(uint32_t*)&hp;
                lo[j] = *(uint32_t*)&lp;
            }
        }
        uint32_t off = swz((uint32_t)w, (uint32_t)oct);
        *(uint4*)(dst + off)              = make_uint4(hi[0], hi[1], hi[2], hi[3]);
        *(uint4*)(dst + XROW_SPLIT + off) = make_uint4(lo[0], lo[1], lo[2], lo[3]);
    }
}

// ---------------- producer staging: batched loads for MLP (64 threads) ------
__device__ __forceinline__ void stage_row_prod(const float* __restrict__ xb,
                                               char* basep, int R, int w0,
                                               int ptid) {
    char* dst = basep + ((R + RING) & (RING - 1)) * ROWBUF;
    const bool rvalid = (unsigned)R < (unsigned)HH;
    const int Rc = rvalid ? R : 0;
    #pragma unroll 1
    for (int k0 = 0; k0 < 1040; k0 += 256) {        // 4 idx per thread per batch
        float f[4][8];
        int wv[4], octv[4];
        #pragma unroll
        for (int u = 0; u < 4; u++) {
            int idx = k0 + u * 64 + ptid;
            bool act = idx < 1040;
            int oct = idx / 130;
            int w   = idx - oct * 130;
            int gw  = w0 - 1 + w;
            bool v = act && rvalid && (unsigned)gw < (unsigned)WW;
            wv[u]   = act ? w : -1;
            octv[u] = oct;
            const float* p = xb + (size_t)(oct * 8) * (HH * WW) +
                             (size_t)Rc * WW + (v ? gw : 0);
            #pragma unroll
            for (int j = 0; j < 8; j++)              // 32 loads in flight/batch
                f[u][j] = v ? p[j * (HH * WW)] : 0.f;
        }
        #pragma unroll
        for (int u = 0; u < 4; u++) {
            if (wv[u] < 0) continue;
            uint32_t hi[4], lo[4];
            #pragma unroll
            for (int j = 0; j < 4; j++) {
                float f0 = f[u][2 * j], f1 = f[u][2 * j + 1];
                __half h0 = __float2half_rn(f0);
                __half h1 = __float2half_rn(f1);
                __half l0 = __float2half_rn(f0 - __half2float(h0));
                __half l1 = __float2half_rn(f1 - __half2float(h1));
                __half2 hp = __halves2half2(h0, h1);
                __half2 lp = __halves2half2(l0, l1);
                hi[j] = *(uint32_t*)&hp;
                lo[j] = *(uint32_t*)&lp;
            }
            uint32_t off = swz((uint32_t)wv[u], (uint32_t)octv[u]);
            *(uint4*)(dst + off)              = make_uint4(hi[0], hi[1], hi[2], hi[3]);
            *(uint4*)(dst + XROW_SPLIT + off) = make_uint4(lo[0], lo[1], lo[2], lo[3]);
        }
    }
}

// ---------------- main fused conv+BN+QuantReLU (16 MMA warps + 2 producers) --
__global__ __launch_bounds__(NTHR, 1)
void conv_kernel(const float* __restrict__ x,
                 float* __restrict__ out) {
    extern __shared__ char dsm[];
    uint32_t raw  = smem_u32(dsm);
    uint32_t base = (raw + 1023) & ~1023u;
    char* basep   = dsm + (base - raw);

    const int tid  = threadIdx.x;
    const int wid  = tid >> 5;
    const int lane = tid & 31;
    const int row_sel = (wid >> 3) & 1;  // compute warps: which of the 2 rows
    const int warp_m  = (wid >> 2) & 1;  // cout 32-block
    const int warp_n  = wid & 3;         // pixel 32-block

    const int w0 = blockIdx.x * 128;
    const int h0 = blockIdx.y * 8;
    const int b  = blockIdx.z;
    const float* xb = x + (size_t)b * CIN * HH * WW;

    // ---- prologue: weights (linear copy, pre-swizzled), 4 rows, BN regs ----
    {
        const uint4* src = (const uint4*)d_Wh;
        uint4* dst = (uint4*)(basep + WB_OFF);
        for (int i = tid; i < WB_BYTES / 16; i += NTHR) dst[i] = src[i];
    }
    stage_row(xb, basep, h0 - 1, w0, tid, NTHR);
    stage_row(xb, basep, h0,     w0, tid, NTHR);
    stage_row(xb, basep, h0 + 1, w0, tid, NTHR);
    stage_row(xb, basep, h0 + 2, w0, tid, NTHR);

    const float sreg = d_s;
    const int base_c = warp_m * 32 + (lane >> 2);
    float gr[4], br[4];
    #pragma unroll
    for (int k = 0; k < 4; k++) {
        gr[k] = d_g[base_c + k * 8];
        br[k] = d_bias[base_c + k * 8];
    }
    __syncthreads();

    // per-lane invariant address parts (compute warps)
    const uint32_t a_base = base + WB_OFF + (uint32_t)(warp_m * 32 + (lane & 15)) * 128;
    const uint32_t a_klo  = (uint32_t)(lane >> 4);
    const uint32_t a_x    = (uint32_t)(lane & 7);
    const uint32_t p_lane = (uint32_t)(warp_n * 32 + (lane & 7) + ((lane >> 4) << 3));
    const uint32_t b_kg   = (uint32_t)((lane >> 3) & 1);

    for (int i = 0; i < 4; i++) {
        if (wid < 16) {
            const int t = h0 + 2 * i + row_sel;

            float acc[2][4][4];
            #pragma unroll
            for (int mt = 0; mt < 2; mt++)
                #pragma unroll
                for (int j = 0; j < 4; j++)
                    #pragma unroll
                    for (int r = 0; r < 4; r++) acc[mt][j][r] = 0.f;

            uint32_t rowoff[3];
            #pragma unroll
            for (int kh = 0; kh < 3; kh++)
                rowoff[kh] = base + (uint32_t)(((t - 1 + kh + RING) & (RING - 1)) * ROWBUF);

            #pragma unroll 1
            for (int tap = 0; tap < 9; tap++) {
                const int kh = tap / 3, kw = tap - 3 * kh;
                const uint32_t atap = a_base + (uint32_t)tap * WTAP;
                const uint32_t brow = rowoff[kh];
                const uint32_t slot = p_lane + (uint32_t)kw;
                const uint32_t sx   = slot & 7u;
                const uint32_t baddr0 = brow + slot * 128u;
                #pragma unroll
                for (int kc = 0; kc < 4; kc++) {
                    uint32_t a0[4], a1[4];
                    const uint32_t ag = ((uint32_t)(kc * 2) + a_klo) ^ a_x;
                    ldsm_x4(a0, atap + (ag << 4));
                    ldsm_x4(a1, atap + 2048u + (ag << 4));
                    const uint32_t bg = (((uint32_t)(kc * 2) + b_kg) ^ sx) << 4;
                    #pragma unroll
                    for (int split = 0; split < 2; split++) {
                        const uint32_t bs0 = baddr0 + (uint32_t)split * XROW_SPLIT + bg;
                        #pragma unroll
                        for (int pb = 0; pb < 2; pb++) {
                            uint32_t r[4];
                            ldsm_x4(r, bs0 + (uint32_t)pb * (16u * 128u));
                            mma16816(acc[0][2 * pb],     a0, r[0], r[1]);
                            mma16816(acc[0][2 * pb + 1], a0, r[2], r[3]);
                            mma16816(acc[1][2 * pb],     a1, r[0], r[1]);
                            mma16816(acc[1][2 * pb + 1], a1, r[2], r[3]);
                        }
                    }
                }
                // signal producers once the dying slots are fully read:
                // rs1 (reads slot t0 in kh0) arrives after tap 2;
                // rs0 (reads slot t0-1 in kh0, slot t0 in kh1) after tap 5.
                if (i < 3) {
                    if (tap == 2 && row_sel == 1) BAR_ARRIVE_1();
                    if (tap == 5 && row_sel == 0) BAR_ARRIVE_1();
                }
            }

            // ---- epilogue: BN+ReLU+uint4 fake-quant, div-free --------------
            #pragma unroll
            for (int mt = 0; mt < 2; mt++) {
                const int c0 = base_c + mt * 16;
                const float g0 = gr[mt * 2],     bf0 = br[mt * 2];
                const float g1 = gr[mt * 2 + 1], bf1 = br[mt * 2 + 1];
                #pragma unroll
                for (int j = 0; j < 4; j++) {
                    const int p = w0 + warp_n * 32 + j * 8 + 2 * (lane & 3);
                    {
                        float y0 = fmaxf(fmaf(acc[mt][j][0], g0, bf0), 0.f);
                        float y1 = fmaxf(fmaf(acc[mt][j][1], g0, bf0), 0.f);
                        float2 o;
                        o.x = fminf(rintf(y0), 15.f) * sreg;
                        o.y = fminf(rintf(y1), 15.f) * sreg;
                        *(float2*)&out[(((size_t)b * COUT + c0) * HH + t) * WW + p] = o;
                    }
                    {
                        float y0 = fmaxf(fmaf(acc[mt][j][2], g1, bf1), 0.f);
                        float y1 = fmaxf(fmaf(acc[mt][j][3], g1, bf1), 0.f);
                        float2 o;
                        o.x = fminf(rintf(y0), 15.f) * sreg;
                        o.y = fminf(rintf(y1), 15.f) * sreg;
                        *(float2*)&out[(((size_t)b * COUT + c0 + 8) * HH + t) * WW + p] = o;
                    }
                }
            }
        } else {
            // ---- producer warps: stage next 2 rows while MMAs run ----------
            if (i < 3) {
                BAR_SYNC_1();            // wait: dying slots fully read
                stage_row_prod(xb, basep, h0 + 2 * i + 3, w0, tid - 512);
                stage_row_prod(xb, basep, h0 + 2 * i + 4, w0, tid - 512);
            }
        }
        __syncthreads();                 // staged rows visible to everyone
    }
}

// ---------------- harness entry ---------------------------------------------
extern "C" void kernel_launch(void* const* d_in, const int* in_sizes, int n_in,
                              void* d_out, int out_size) {
    const float* x     = (const float*)d_in[0];
    const float* W     = (const float*)d_in[1];
    const float* gamma = (const float*)d_in[2];
    const float* beta  = (const float*)d_in[3];
    const float* mean  = (const float*)d_in[4];
    const float* var   = (const float*)d_in[5];
    const float* act   = (const float*)d_in[6];
    float* out = (float*)d_out;
    (void)in_sizes; (void)n_in; (void)out_size;

    cudaFuncSetAttribute(conv_kernel, cudaFuncAttributeMaxDynamicSharedMemorySize,
                         SMEM_REQ);
    prep_kernel<<<COUT, 256>>>(W, gamma, beta, mean, var, act);
    dim3 grid(WW / 128, HH / 8, BATCH);
    conv_kernel<<<grid, NTHR, SMEM_REQ>>>(x, out);
}

// round 15
// speedup vs baseline: 1.1628x; 1.1628x over previous
#include <cuda_runtime.h>
#include <cuda_fp16.h>
#include <cstdint>

#define HH    256
#define WW    256
#define BATCH 16
#define CIN   64
#define COUT  64

// ---- smem layout (byte offsets from 1024-aligned base) ---------------------
#define RING       4
#define XROW_SPLIT (130 * 128)            // 16640 B: one split (hi or lo) of a row
#define ROWBUF     (2 * XROW_SPLIT)       // 33280
#define XS_BYTES   (RING * ROWBUF)        // 133120
#define WB_OFF     XS_BYTES
#define WTAP       8192                   // 64 co x 64 ci fp16, swizzled
#define WB_BYTES   (9 * WTAP)             // 73728
#define SMEM_REQ   (WB_OFF + WB_BYTES + 1024 + 64)  // align slack -> 207936

// Scratch globals
__device__ __align__(16) __half d_Wh[9 * 64 * 64];  // [tap][co][ci] pre-swizzled
__device__ float d_g[COUT];      // (gamma*istd*wscale)/s   -- quant-folded
__device__ float d_bias[COUT];   // (beta - mean*gamma*istd)/s
__device__ float d_s;            // act quant step s

__device__ __forceinline__ uint32_t smem_u32(const void* p) {
    uint32_t a;
    asm("{ .reg .u64 t; cvta.to.shared.u64 t, %1; cvt.u32.u64 %0, t; }" : "=r"(a) : "l"(p));
    return a;
}
__device__ __forceinline__ void ldsm_x4(uint32_t* r, uint32_t addr) {
    asm volatile("ldmatrix.sync.aligned.m8n8.x4.shared.b16 {%0,%1,%2,%3}, [%4];"
                 : "=r"(r[0]), "=r"(r[1]), "=r"(r[2]), "=r"(r[3]) : "r"(addr));
}
__device__ __forceinline__ void mma16816(float* c, const uint32_t* a,
                                         uint32_t b0, uint32_t b1) {
    asm volatile("mma.sync.aligned.m16n8k16.row.col.f32.f16.f16.f32 "
                 "{%0,%1,%2,%3}, {%4,%5,%6,%7}, {%8,%9}, {%0,%1,%2,%3};"
                 : "+f"(c[0]), "+f"(c[1]), "+f"(c[2]), "+f"(c[3])
                 : "r"(a[0]), "r"(a[1]), "r"(a[2]), "r"(a[3]), "r"(b0), "r"(b1));
}

// swizzled byte offset for (slot row, 16B group): conflict-free ldsm w/o padding
__device__ __forceinline__ uint32_t swz(uint32_t slot, uint32_t g) {
    return slot * 128u + ((g ^ (slot & 7u)) << 4);
}

// ---------------- prep: int4 fake-quant weights + BN/act-quant fold ---------
__global__ void prep_kernel(const float* __restrict__ W,
                            const float* __restrict__ gamma,
                            const float* __restrict__ beta,
                            const float* __restrict__ mean,
                            const float* __restrict__ var,
                            const float* __restrict__ act_scale) {
    int co = blockIdx.x;
    __shared__ float red[256];
    float m = 0.f;
    for (int i = threadIdx.x; i < CIN * 9; i += 256)
        m = fmaxf(m, fabsf(W[co * CIN * 9 + i]));
    red[threadIdx.x] = m;
    __syncthreads();
    for (int s = 128; s > 0; s >>= 1) {
        if (threadIdx.x < s)
            red[threadIdx.x] = fmaxf(red[threadIdx.x], red[threadIdx.x + s]);
        __syncthreads();
    }
    float scale = fmaxf(red[0] / 7.0f, 1e-8f);

    for (int i = threadIdx.x; i < CIN * 9; i += 256) {
        int ci = i / 9, r = i - ci * 9;
        float n = rintf(W[co * CIN * 9 + i] / scale);   // round-half-even
        n = fminf(fmaxf(n, -7.f), 7.f);                 // small int -> fp16 exact
        d_Wh[r * 4096 + co * 64 + (((ci >> 3) ^ (co & 7)) << 3) + (ci & 7)] =
            __float2half_rn(n);
    }
    if (threadIdx.x == 0) {
        float s = fmaxf(act_scale[0], 1e-8f);
        float istd = 1.0f / sqrtf(var[co] + 1e-5f);
        // fold weight scale AND 1/s into the BN affine (kills per-output div)
        d_g[co]    = gamma[co] * istd * scale / s;
        d_bias[co] = (beta[co] - mean[co] * gamma[co] * istd) / s;
        if (co == 0) d_s = s;
    }
}

// ---------------- stage one input row (prologue only) -----------------------
__device__ __forceinline__ void stage_row(const float* __restrict__ xb,
                                          char* basep, int R, int w0, int tid) {
    char* dst = basep + ((R + RING) & (RING - 1)) * ROWBUF;
    bool rvalid = (unsigned)R < (unsigned)HH;
    for (int idx = tid; idx < 130 * 8; idx += 512) {
        int oct = idx / 130;
        int w   = idx - oct * 130;
        int gw  = w0 - 1 + w;
        uint32_t hi[4] = {0, 0, 0, 0}, lo[4] = {0, 0, 0, 0};
        if (rvalid && (unsigned)gw < (unsigned)WW) {
            const float* p = xb + (size_t)(oct * 8) * (HH * WW) + R * WW + gw;
            #pragma unroll
            for (int j = 0; j < 4; j++) {
                float f0 = p[(2 * j)     * (HH * WW)];
                float f1 = p[(2 * j + 1) * (HH * WW)];
                __half h0 = __float2half_rn(f0);
                __half h1 = __float2half_rn(f1);
                __half l0 = __float2half_rn(f0 - __half2float(h0));
                __half l1 = __float2half_rn(f1 - __half2float(h1));
                __half2 hp = __halves2half2(h0, h1);
                __half2 lp = __halves2half2(l0, l1);
                hi[j] = *(uint32_t*)&hp;
                lo[j] = *(uint32_t*)&lp;
            }
        }
        uint32_t off = swz((uint32_t)w, (uint32_t)oct);
        *(uint4*)(dst + off)              = make_uint4(hi[0], hi[1], hi[2], hi[3]);
        *(uint4*)(dst + XROW_SPLIT + off) = make_uint4(lo[0], lo[1], lo[2], lo[3]);
    }
}

// quad-item decode: qr in [0,2080) -> (och 0..15, w 0..129); exact for this range
#define QDECODE(qr, och, w) do { \
    och = ((qr) * 4033) >> 19;   \
    w   = (qr) - och * 130;      \
} while (0)

// ---------------- main fused conv+BN+QuantReLU (HMMA m32n32, 16 warps) ------
__global__ __launch_bounds__(512, 1)
void conv_kernel(const float* __restrict__ x,
                 float* __restrict__ out) {
    extern __shared__ char dsm[];
    uint32_t raw  = smem_u32(dsm);
    uint32_t base = (raw + 1023) & ~1023u;
    char* basep   = dsm + (base - raw);

    const int tid  = threadIdx.x;
    const int wid  = tid >> 5;
    const int lane = tid & 31;
    const int row_sel = wid >> 3;        // which of the 2 rows this warp computes
    const int warp_m  = (wid >> 2) & 1;  // cout 32-block
    const int warp_n  = wid & 3;         // pixel 32-block

    const int w0 = blockIdx.x * 128;
    const int h0 = blockIdx.y * 8;
    const int b  = blockIdx.z;
    const float* xb = x + (size_t)b * CIN * HH * WW;

    // ---- prologue: weights (linear copy, pre-swizzled), 4 rows, BN regs ----
    {
        const uint4* src = (const uint4*)d_Wh;
        uint4* dst = (uint4*)(basep + WB_OFF);
        for (int i = tid; i < WB_BYTES / 16; i += 512) dst[i] = src[i];
    }
    stage_row(xb, basep, h0 - 1, w0, tid);
    stage_row(xb, basep, h0,     w0, tid);
    stage_row(xb, basep, h0 + 1, w0, tid);
    stage_row(xb, basep, h0 + 2, w0, tid);

    const float sreg = d_s;
    const int base_c = warp_m * 32 + (lane >> 2);
    float gr[4], br[4];
    #pragma unroll
    for (int k = 0; k < 4; k++) {
        gr[k] = d_g[base_c + k * 8];
        br[k] = d_bias[base_c + k * 8];
    }
    __syncthreads();

    // per-lane invariant address parts
    const uint32_t a_base = base + WB_OFF + (uint32_t)(warp_m * 32 + (lane & 15)) * 128;
    const uint32_t a_klo  = (uint32_t)(lane >> 4);
    const uint32_t a_x    = (uint32_t)(lane & 7);
    const uint32_t p_lane = (uint32_t)(warp_n * 32 + (lane & 7) + ((lane >> 4) << 3));
    const uint32_t b_kg   = (uint32_t)((lane >> 3) & 1);

    for (int i = 0; i < 4; i++) {
        const int t = h0 + 2 * i + row_sel;    // this warp's output row
        const int rowA = h0 + 2 * i + 3;       // first row to stage this iter

        // ---- fire-and-forget staging loads (complete during MMA phase) -----
        float st[9][4];
        if (i < 3) {
            #pragma unroll
            for (int k = 0; k < 9; k++) {
                int qr, rr;
                bool act;
                if (k < 8) { qr = tid + ((k & 3) << 9); rr = k >> 2; act = true; }
                else       { qr = 2048 + (tid & 31);    rr = tid >> 5; act = (tid < 64); }
                int och, w;
                QDECODE(qr, och, w);
                const int oct = och >> 1, half = och & 1;
                const int R   = rowA + rr;
                const int gw  = w0 - 1 + w;
                st[k][0] = 0.f; st[k][1] = 0.f; st[k][2] = 0.f; st[k][3] = 0.f;
                if (act && R < HH && (unsigned)gw < (unsigned)WW) {
                    const float* p = xb + (size_t)(oct * 8 + half * 4) * (HH * WW) +
                                     (size_t)R * WW + gw;
                    asm volatile("ld.global.nc.f32 %0, [%1];"        : "=f"(st[k][0]) : "l"(p));
                    asm volatile("ld.global.nc.f32 %0, [%1+262144];" : "=f"(st[k][1]) : "l"(p));
                    asm volatile("ld.global.nc.f32 %0, [%1+524288];" : "=f"(st[k][2]) : "l"(p));
                    asm volatile("ld.global.nc.f32 %0, [%1+786432];" : "=f"(st[k][3]) : "l"(p));
                }
            }
        }

        float acc[2][4][4];
        #pragma unroll
        for (int mt = 0; mt < 2; mt++)
            #pragma unroll
            for (int j = 0; j < 4; j++)
                #pragma unroll
                for (int r = 0; r < 4; r++) acc[mt][j][r] = 0.f;

        uint32_t rowoff[3];
        #pragma unroll
        for (int kh = 0; kh < 3; kh++)
            rowoff[kh] = base + (uint32_t)(((t - 1 + kh + RING) & (RING - 1)) * ROWBUF);

        #pragma unroll 1
        for (int tap = 0; tap < 9; tap++) {
            const int kh = tap / 3, kw = tap - 3 * kh;
            const uint32_t atap = a_base + (uint32_t)tap * WTAP;
            const uint32_t brow = rowoff[kh];
            const uint32_t slot = p_lane + (uint32_t)kw;
            const uint32_t sx   = slot & 7u;
            const uint32_t baddr0 = brow + slot * 128u;
            #pragma unroll
            for (int kc = 0; kc < 4; kc++) {
                uint32_t a0[4], a1[4];
                const uint32_t ag = ((uint32_t)(kc * 2) + a_klo) ^ a_x;
                ldsm_x4(a0, atap + (ag << 4));
                ldsm_x4(a1, atap + 2048u + (ag << 4));
                const uint32_t bg = (((uint32_t)(kc * 2) + b_kg) ^ sx) << 4;
                #pragma unroll
                for (int split = 0; split < 2; split++) {
                    const uint32_t bs0 = baddr0 + (uint32_t)split * XROW_SPLIT + bg;
                    #pragma unroll
                    for (int pb = 0; pb < 2; pb++) {
                        uint32_t r[4];
                        ldsm_x4(r, bs0 + (uint32_t)pb * (16u * 128u));
                        mma16816(acc[0][2 * pb],     a0, r[0], r[1]);
                        mma16816(acc[0][2 * pb + 1], a0, r[2], r[3]);
                        mma16816(acc[1][2 * pb],     a1, r[0], r[1]);
                        mma16816(acc[1][2 * pb + 1], a1, r[2], r[3]);
                    }
                }
            }
        }

        // ---- epilogue: BN+ReLU+uint4 fake-quant (no smem; before sync) -----
        #pragma unroll
        for (int mt = 0; mt < 2; mt++) {
            const int c0 = base_c + mt * 16;
            const float g0 = gr[mt * 2],     bf0 = br[mt * 2];
            const float g1 = gr[mt * 2 + 1], bf1 = br[mt * 2 + 1];
            #pragma unroll
            for (int j = 0; j < 4; j++) {
                const int p = w0 + warp_n * 32 + j * 8 + 2 * (lane & 3);
                {
                    float y0 = fmaxf(fmaf(acc[mt][j][0], g0, bf0), 0.f);
                    float y1 = fmaxf(fmaf(acc[mt][j][1], g0, bf0), 0.f);
                    float2 o;
                    o.x = fminf(rintf(y0), 15.f) * sreg;
                    o.y = fminf(rintf(y1), 15.f) * sreg;
                    *(float2*)&out[(((size_t)b * COUT + c0) * HH + t) * WW + p] = o;
                }
                {
                    float y0 = fmaxf(fmaf(acc[mt][j][2], g1, bf1), 0.f);
                    float y1 = fmaxf(fmaf(acc[mt][j][3], g1, bf1), 0.f);
                    float2 o;
                    o.x = fminf(rintf(y0), 15.f) * sreg;
                    o.y = fminf(rintf(y1), 15.f) * sreg;
                    *(float2*)&out[(((size_t)b * COUT + c0 + 8) * HH + t) * WW + p] = o;
                }
            }
        }

        __syncthreads();                 // #1: all smem reads of this iter done

        // ---- convert + STS the pre-loaded rows into freed ring slots -------
        if (i < 3) {
            #pragma unroll
            for (int k = 0; k < 9; k++) {
                int qr, rr;
                bool act;
                if (k < 8) { qr = tid + ((k & 3) << 9); rr = k >> 2; act = true; }
                else       { qr = 2048 + (tid & 31);    rr = tid >> 5; act = (tid < 64); }
                if (!act) continue;
                int och, w;
                QDECODE(qr, och, w);
                const int oct = och >> 1, half = och & 1;
                const int R   = rowA + rr;
                char* dst = basep + ((R + RING) & (RING - 1)) * ROWBUF;
                uint32_t off = swz((uint32_t)w, (uint32_t)oct) + (uint32_t)half * 8u;

                __half h0 = __float2half_rn(st[k][0]);
                __half h1 = __float2half_rn(st[k][1]);
                __half h2 = __float2half_rn(st[k][2]);
                __half h3 = __float2half_rn(st[k][3]);
                __half l0 = __float2half_rn(st[k][0] - __half2float(h0));
                __half l1 = __float2half_rn(st[k][1] - __half2float(h1));
                __half l2 = __float2half_rn(st[k][2] - __half2float(h2));
                __half l3 = __float2half_rn(st[k][3] - __half2float(h3));
                __half2 hp0 = __halves2half2(h0, h1), hp1 = __halves2half2(h2, h3);
                __half2 lp0 = __halves2half2(l0, l1), lp1 = __halves2half2(l2, l3);
                uint2 hv, lv;
                hv.x = *(uint32_t*)&hp0; hv.y = *(uint32_t*)&hp1;
                lv.x = *(uint32_t*)&lp0; lv.y = *(uint32_t*)&lp1;
                *(uint2*)(dst + off)              = hv;
                *(uint2*)(dst + XROW_SPLIT + off) = lv;
            }
        }
        __syncthreads();                 // #2: staged rows visible
    }
}

// ---------------- harness entry ---------------------------------------------
extern "C" void kernel_launch(void* const* d_in, const int* in_sizes, int n_in,
                              void* d_out, int out_size) {
    const float* x     = (const float*)d_in[0];
    const float* W     = (const float*)d_in[1];
    const float* gamma = (const float*)d_in[2];
    const float* beta  = (const float*)d_in[3];
    const float* mean  = (const float*)d_in[4];
    const float* var   = (const float*)d_in[5];
    const float* act   = (const float*)d_in[6];
    float* out = (float*)d_out;
    (void)in_sizes; (void)n_in; (void)out_size;

    cudaFuncSetAttribute(conv_kernel, cudaFuncAttributeMaxDynamicSharedMemorySize,
                         SMEM_REQ);
    prep_kernel<<<COUT, 256>>>(W, gamma, beta, mean, var, act);
    dim3 grid(WW / 128, HH / 8, BATCH);
    conv_kernel<<<grid, 512, SMEM_REQ>>>(x, out);
}